// round 7
// baseline (speedup 1.0000x reference)
#include <cuda_runtime.h>
#include <cuda_bf16.h>
#include <math.h>

#define NR   8192     // rows of z
#define HD   256      // feature dim
#define NC   64       // clusters
#define RPB  32       // rows per block
#define TPB  256      // 8 warps: 2 warp_m x 4 warp_n, warp tile m16n16
#define NBLK (NR / RPB)   // 256 blocks, all resident at 2 blocks/SM

// smem: zh [32][256]bf16=16KB, ch/cl [64][256]bf16=32KB each; stride 512B, XOR-swizzled
#define OFF_ZH 0
#define OFF_CH 16384
#define OFF_CL 49152
#define SMEM_B 81920

__device__ float g_partT[NC * NBLK];  // transposed partial colsums [col][block]
__device__ unsigned int g_arrive;     // epoch ticket counter (static zero-init)

#define LDSM4(r, addr) \
    asm volatile("ldmatrix.sync.aligned.m8n8.x4.shared.b16 {%0,%1,%2,%3}, [%4];" \
        : "=r"((r)[0]), "=r"((r)[1]), "=r"((r)[2]), "=r"((r)[3]) : "r"(addr))

#define MMA16816(d, a, b0, b1) \
    asm volatile("mma.sync.aligned.m16n8k16.row.col.f32.bf16.bf16.f32 " \
        "{%0,%1,%2,%3},{%4,%5,%6,%7},{%8,%9},{%0,%1,%2,%3};" \
        : "+f"((d)[0]), "+f"((d)[1]), "+f"((d)[2]), "+f"((d)[3]) \
        : "r"((a)[0]), "r"((a)[1]), "r"((a)[2]), "r"((a)[3]), "r"(b0), "r"(b1))

__device__ __forceinline__ unsigned bf2_bits(__nv_bfloat162 h) {
    return *reinterpret_cast<unsigned*>(&h);
}
__device__ __forceinline__ float fsqrt_ap(float x) {
    float r; asm("sqrt.approx.ftz.f32 %0, %1;" : "=f"(r) : "f"(x)); return r;
}
__device__ __forceinline__ float frcp_ap(float x) {
    float r; asm("rcp.approx.ftz.f32 %0, %1;" : "=f"(r) : "f"(x)); return r;
}

__global__ void __launch_bounds__(TPB, 2)
fused_kernel(const float* __restrict__ z, const float* __restrict__ cent,
             float* __restrict__ Q, float* __restrict__ P) {
    extern __shared__ char smem[];
    char* zh = smem + OFF_ZH;
    char* ch = smem + OFF_CH;
    char* cl = smem + OFF_CL;
    __shared__ float s_zn[RPB], s_cn[NC];
    __shared__ float s_rs[RPB], s_cs[NC], s_ct[NC], s_pr[RPB];

    const int t = threadIdx.x;
    const unsigned sb = (unsigned)__cvta_generic_to_shared(smem);

    if (t < NC) { s_cs[t] = 0.f; s_ct[t] = 0.f; }
    if (t < RPB) { s_rs[t] = 0.f; s_pr[t] = 0.f; }

    // ---- Phase 1a: z tile -> hi bf16 smem + row norms (8 lanes/row) ----
    {
        const float4* g4 = (const float4*)(z + (size_t)blockIdx.x * RPB * HD);
        const int row = t >> 3, l8 = t & 7;
        float acc = 0.f;
        #pragma unroll
        for (int j = 0; j < 8; j++) {
            const int c4 = l8 + 8 * j;
            float4 v = g4[row * (HD / 4) + c4];
            acc = fmaf(v.x, v.x, acc);
            acc = fmaf(v.y, v.y, acc);
            acc = fmaf(v.z, v.z, acc);
            acc = fmaf(v.w, v.w, acc);
            __nv_bfloat162 h01 = __floats2bfloat162_rn(v.x, v.y);
            __nv_bfloat162 h23 = __floats2bfloat162_rn(v.z, v.w);
            const int byteoff = 8 * c4;
            const unsigned off = row * 512 +
                ((((byteoff >> 4) ^ (row & 7)) << 4) | (byteoff & 15));
            *(uint2*)(zh + off) = make_uint2(bf2_bits(h01), bf2_bits(h23));
        }
        acc += __shfl_xor_sync(0xffffffffu, acc, 1);
        acc += __shfl_xor_sync(0xffffffffu, acc, 2);
        acc += __shfl_xor_sync(0xffffffffu, acc, 4);
        if (l8 == 0) s_zn[row] = acc;
    }

    // ---- Phase 1b: centroids -> hi/lo bf16 smem + norms (4 lanes/row) ----
    {
        const float4* g4 = (const float4*)cent;
        const int row = t >> 2, l4 = t & 3;
        float acc = 0.f;
        #pragma unroll
        for (int j = 0; j < 16; j++) {
            const int c4 = l4 + 4 * j;
            float4 v = g4[row * (HD / 4) + c4];
            acc = fmaf(v.x, v.x, acc);
            acc = fmaf(v.y, v.y, acc);
            acc = fmaf(v.z, v.z, acc);
            acc = fmaf(v.w, v.w, acc);
            __nv_bfloat162 h01 = __floats2bfloat162_rn(v.x, v.y);
            __nv_bfloat162 h23 = __floats2bfloat162_rn(v.z, v.w);
            float lx = v.x - __low2float(h01);
            float ly = v.y - __high2float(h01);
            float lz = v.z - __low2float(h23);
            float lw = v.w - __high2float(h23);
            __nv_bfloat162 l01 = __floats2bfloat162_rn(lx, ly);
            __nv_bfloat162 l23 = __floats2bfloat162_rn(lz, lw);
            const int byteoff = 8 * c4;
            const unsigned off = row * 512 +
                ((((byteoff >> 4) ^ (row & 7)) << 4) | (byteoff & 15));
            *(uint2*)(ch + off) = make_uint2(bf2_bits(h01), bf2_bits(h23));
            *(uint2*)(cl + off) = make_uint2(bf2_bits(l01), bf2_bits(l23));
        }
        acc += __shfl_xor_sync(0xffffffffu, acc, 1);
        acc += __shfl_xor_sync(0xffffffffu, acc, 2);
        if (l4 == 0) s_cn[row] = acc;
    }
    __syncthreads();

    // ---- Phase 2: GEMM mainloop (2-term: zh*ch + zh*cl), warp m16n16 ----
    const int lane = t & 31, wid = t >> 5;
    const int wm = wid >> 2, wn = wid & 3;
    const int tile = lane >> 3, rit = lane & 7;

    const int arow = wm * 16 + rit + 8 * (tile & 1);
    const int acb = tile >> 1;
    const unsigned azh = sb + OFF_ZH + arow * 512;
    const int axor = arow & 7;

    const int brow = wn * 16 + rit + 8 * (tile >> 1);
    const int bcb = tile & 1;
    const unsigned bch = sb + OFF_CH + brow * 512;
    const unsigned bcl = sb + OFF_CL + brow * 512;
    const int bxor = brow & 7;

    float d0[4] = {0.f, 0.f, 0.f, 0.f};
    float d1[4] = {0.f, 0.f, 0.f, 0.f};

    #pragma unroll
    for (int ks = 0; ks < 16; ks++) {
        const unsigned aoff = (unsigned)(((2 * ks + acb) ^ axor) << 4);
        const unsigned boff = (unsigned)(((2 * ks + bcb) ^ bxor) << 4);
        unsigned ah[4], bhf[4], blf[4];
        LDSM4(ah, azh + aoff);
        LDSM4(bhf, bch + boff);
        LDSM4(blf, bcl + boff);
        MMA16816(d0, ah, bhf[0], bhf[1]);
        MMA16816(d1, ah, bhf[2], bhf[3]);
        MMA16816(d0, ah, blf[0], blf[1]);
        MMA16816(d1, ah, blf[2], blf[3]);
    }

    // ---- Phase 3: epilogue -> Q ----
    const int gid = lane >> 2, tig = lane & 3;
    const int R0 = wm * 16 + gid, R1 = R0 + 8;
    const float znA = s_zn[R0], znB = s_zn[R1];
    const int c00 = wn * 16 + 2 * tig;
    const int c10 = c00 + 8;
    const float cnA0 = s_cn[c00], cnA1 = s_cn[c00 + 1];
    const float cnB0 = s_cn[c10], cnB1 = s_cn[c10 + 1];

    float q00 = frcp_ap(1.f + fsqrt_ap(fmaxf(fmaf(-2.f, d0[0], znA + cnA0), 0.f)));
    float q01 = frcp_ap(1.f + fsqrt_ap(fmaxf(fmaf(-2.f, d0[1], znA + cnA1), 0.f)));
    float q02 = frcp_ap(1.f + fsqrt_ap(fmaxf(fmaf(-2.f, d0[2], znB + cnA0), 0.f)));
    float q03 = frcp_ap(1.f + fsqrt_ap(fmaxf(fmaf(-2.f, d0[3], znB + cnA1), 0.f)));
    float q10 = frcp_ap(1.f + fsqrt_ap(fmaxf(fmaf(-2.f, d1[0], znA + cnB0), 0.f)));
    float q11 = frcp_ap(1.f + fsqrt_ap(fmaxf(fmaf(-2.f, d1[1], znA + cnB1), 0.f)));
    float q12 = frcp_ap(1.f + fsqrt_ap(fmaxf(fmaf(-2.f, d1[2], znB + cnB0), 0.f)));
    float q13 = frcp_ap(1.f + fsqrt_ap(fmaxf(fmaf(-2.f, d1[3], znB + cnB1), 0.f)));

    float rs0 = (q00 + q01) + (q10 + q11);
    float rs1 = (q02 + q03) + (q12 + q13);
    rs0 += __shfl_xor_sync(0xffffffffu, rs0, 1);
    rs0 += __shfl_xor_sync(0xffffffffu, rs0, 2);
    rs1 += __shfl_xor_sync(0xffffffffu, rs1, 1);
    rs1 += __shfl_xor_sync(0xffffffffu, rs1, 2);
    if (tig == 0) { atomicAdd(&s_rs[R0], rs0); atomicAdd(&s_rs[R1], rs1); }
    __syncthreads();

    const float ir0 = frcp_ap(s_rs[R0]), ir1 = frcp_ap(s_rs[R1]);
    q00 *= ir0; q01 *= ir0; q10 *= ir0; q11 *= ir0;
    q02 *= ir1; q03 *= ir1; q12 *= ir1; q13 *= ir1;

    const int gA = blockIdx.x * RPB + R0;
    const int gB = blockIdx.x * RPB + R1;
    *(float2*)(Q + (size_t)gA * NC + c00) = make_float2(q00, q01);
    *(float2*)(Q + (size_t)gB * NC + c00) = make_float2(q02, q03);
    *(float2*)(Q + (size_t)gA * NC + c10) = make_float2(q10, q11);
    *(float2*)(Q + (size_t)gB * NC + c10) = make_float2(q12, q13);

    float cA0 = q00 + q02, cA1 = q01 + q03;
    float cB0 = q10 + q12, cB1 = q11 + q13;
    #pragma unroll
    for (int m = 4; m <= 16; m <<= 1) {
        cA0 += __shfl_xor_sync(0xffffffffu, cA0, m);
        cA1 += __shfl_xor_sync(0xffffffffu, cA1, m);
        cB0 += __shfl_xor_sync(0xffffffffu, cB0, m);
        cB1 += __shfl_xor_sync(0xffffffffu, cB1, m);
    }
    if (lane < 4) {
        atomicAdd(&s_cs[c00], cA0);
        atomicAdd(&s_cs[c00 + 1], cA1);
        atomicAdd(&s_cs[c10], cB0);
        atomicAdd(&s_cs[c10 + 1], cB1);
    }
    __syncthreads();

    // publish block partial colsums (transposed: [col][block])
    if (t < NC) g_partT[t * NBLK + blockIdx.x] = s_cs[t];
    __threadfence();
    __syncthreads();

    // ---- grid sync: all 256 blocks resident (2/SM), epoch ticket ----
    if (t == 0) {
        unsigned ticket;
        asm volatile("atom.global.add.release.gpu.u32 %0, [%1], 1;"
                     : "=r"(ticket) : "l"(&g_arrive) : "memory");
        const unsigned target = (ticket / NBLK + 1u) * NBLK;
        unsigned v;
        do {
            asm volatile("ld.global.acquire.gpu.u32 %0, [%1];"
                         : "=r"(v) : "l"(&g_arrive) : "memory");
        } while (v < target);
    }
    __syncthreads();
    __threadfence();

    // total column sums: 4 segments x 64 contiguous floats per column
    {
        const int col = t >> 2, seg = t & 3;
        const float4* p4 = (const float4*)(g_partT + col * NBLK + seg * 64);
        float s = 0.f;
        #pragma unroll
        for (int j = 0; j < 16; j++) {
            float4 u = __ldcg(p4 + j);
            s += ((u.x + u.y) + (u.z + u.w));
        }
        s += __shfl_xor_sync(0xffffffffu, s, 1);
        s += __shfl_xor_sync(0xffffffffu, s, 2);
        if (seg == 0) s_ct[col] = s;
    }
    __syncthreads();

    // ---- Phase 4: P from in-register Q ----
    const float icA0 = frcp_ap(s_ct[c00]), icA1 = frcp_ap(s_ct[c00 + 1]);
    const float icB0 = frcp_ap(s_ct[c10]), icB1 = frcp_ap(s_ct[c10 + 1]);

    float p00 = q00 * q00 * icA0, p01 = q01 * q01 * icA1;
    float p02 = q02 * q02 * icA0, p03 = q03 * q03 * icA1;
    float p10 = q10 * q10 * icB0, p11 = q11 * q11 * icB1;
    float p12 = q12 * q12 * icB0, p13 = q13 * q13 * icB1;

    float ps0 = (p00 + p01) + (p10 + p11);
    float ps1 = (p02 + p03) + (p12 + p13);
    ps0 += __shfl_xor_sync(0xffffffffu, ps0, 1);
    ps0 += __shfl_xor_sync(0xffffffffu, ps0, 2);
    ps1 += __shfl_xor_sync(0xffffffffu, ps1, 1);
    ps1 += __shfl_xor_sync(0xffffffffu, ps1, 2);
    if (tig == 0) { atomicAdd(&s_pr[R0], ps0); atomicAdd(&s_pr[R1], ps1); }
    __syncthreads();

    const float ip0 = frcp_ap(s_pr[R0]), ip1 = frcp_ap(s_pr[R1]);
    *(float2*)(P + (size_t)gA * NC + c00) = make_float2(p00 * ip0, p01 * ip0);
    *(float2*)(P + (size_t)gB * NC + c00) = make_float2(p02 * ip1, p03 * ip1);
    *(float2*)(P + (size_t)gA * NC + c10) = make_float2(p10 * ip0, p11 * ip0);
    *(float2*)(P + (size_t)gB * NC + c10) = make_float2(p12 * ip1, p13 * ip1);
}

extern "C" void kernel_launch(void* const* d_in, const int* in_sizes, int n_in,
                              void* d_out, int out_size) {
    const float* z    = (const float*)d_in[0];   // (8192, 256) f32
    const float* cent = (const float*)d_in[1];   // (64, 256)   f32
    float* Q = (float*)d_out;
    float* P = Q + (size_t)NR * NC;

    cudaFuncSetAttribute(fused_kernel, cudaFuncAttributeMaxDynamicSharedMemorySize, SMEM_B);
    fused_kernel<<<NBLK, TPB, SMEM_B>>>(z, cent, Q, P);
}

// round 8
// speedup vs baseline: 1.3836x; 1.3836x over previous
#include <cuda_runtime.h>
#include <cuda_bf16.h>
#include <math.h>

#define NR   8192     // rows of z
#define HD   256      // feature dim
#define NC   64       // clusters
#define RPB  64       // rows per block
#define TPB  512      // 16 warps: 4 warp_m x 4 warp_n, warp tile m16n16
#define NBLK (NR / RPB)   // 128 blocks, one wave, 1 block/SM

// fp32 tiles in smem, row stride 1024B (= 64 x 16B chunks), XOR-swizzled
#define OFF_Z  0
#define OFF_C  65536
#define SMEM_B 131072

__device__ float g_partT[NC * NBLK];  // transposed partial colsums [col][block]
__device__ unsigned int g_arrive;     // epoch ticket counter (static zero-init)

#define LDSM4(r, addr) \
    asm volatile("ldmatrix.sync.aligned.m8n8.x4.shared.b16 {%0,%1,%2,%3}, [%4];" \
        : "=r"((r)[0]), "=r"((r)[1]), "=r"((r)[2]), "=r"((r)[3]) : "r"(addr))

#define MMA_TF32(d, a, b0, b1) \
    asm volatile("mma.sync.aligned.m16n8k8.row.col.f32.tf32.tf32.f32 " \
        "{%0,%1,%2,%3},{%4,%5,%6,%7},{%8,%9},{%0,%1,%2,%3};" \
        : "+f"((d)[0]), "+f"((d)[1]), "+f"((d)[2]), "+f"((d)[3]) \
        : "r"((a)[0]), "r"((a)[1]), "r"((a)[2]), "r"((a)[3]), "r"(b0), "r"(b1))

#define CP_ASYNC16(dst, src) \
    asm volatile("cp.async.cg.shared.global [%0], [%1], 16;" \
        :: "r"(dst), "l"(src) : "memory")

__device__ __forceinline__ float fsqrt_ap(float x) {
    float r; asm("sqrt.approx.ftz.f32 %0, %1;" : "=f"(r) : "f"(x)); return r;
}
__device__ __forceinline__ float frcp_ap(float x) {
    float r; asm("rcp.approx.ftz.f32 %0, %1;" : "=f"(r) : "f"(x)); return r;
}
// swizzled byte offset of 16B chunk (row, c) within a tile
__device__ __forceinline__ unsigned swz(int row, int c) {
    return (unsigned)(row * 1024 + (((c ^ (row & 7)) << 4)));
}

__global__ void __launch_bounds__(TPB, 1)
fused_kernel(const float* __restrict__ z, const float* __restrict__ cent,
             float* __restrict__ Q, float* __restrict__ P) {
    extern __shared__ char smem[];
    __shared__ float s_zn[RPB], s_cn[NC];
    __shared__ float s_rs[RPB], s_cs[NC], s_ct[NC], s_pr[RPB];

    const int t = threadIdx.x;
    const unsigned sb = (unsigned)__cvta_generic_to_shared(smem);

    // ---- Phase 0: async copy z tile (64x256 f32) + centroids (64x256 f32) ----
    const int row = t >> 3, c8 = t & 7;       // 64 rows x 8 chunk-lanes
    {
        const float* zg = z + (size_t)blockIdx.x * RPB * HD + row * HD;
        const float* cg = cent + row * HD;
        #pragma unroll
        for (int j = 0; j < 8; j++) {
            const int c = c8 + 8 * j;
            CP_ASYNC16(sb + OFF_Z + swz(row, c), zg + 4 * c);
            CP_ASYNC16(sb + OFF_C + swz(row, c), cg + 4 * c);
        }
    }
    asm volatile("cp.async.commit_group;" ::: "memory");

    if (t < NC) { s_cs[t] = 0.f; s_ct[t] = 0.f; }
    if (t < RPB) { s_rs[t] = 0.f; s_pr[t] = 0.f; }

    asm volatile("cp.async.wait_group 0;" ::: "memory");
    __syncthreads();

    // ---- Phase 1: norms from smem (each lane re-reads its own chunks) ----
    {
        float az = 0.f, ac = 0.f;
        #pragma unroll
        for (int j = 0; j < 8; j++) {
            const int c = c8 + 8 * j;
            float4 vz = *(const float4*)(smem + OFF_Z + swz(row, c));
            float4 vc = *(const float4*)(smem + OFF_C + swz(row, c));
            az = fmaf(vz.x, vz.x, az); az = fmaf(vz.y, vz.y, az);
            az = fmaf(vz.z, vz.z, az); az = fmaf(vz.w, vz.w, az);
            ac = fmaf(vc.x, vc.x, ac); ac = fmaf(vc.y, vc.y, ac);
            ac = fmaf(vc.z, vc.z, ac); ac = fmaf(vc.w, vc.w, ac);
        }
        az += __shfl_xor_sync(0xffffffffu, az, 1);
        az += __shfl_xor_sync(0xffffffffu, az, 2);
        az += __shfl_xor_sync(0xffffffffu, az, 4);
        ac += __shfl_xor_sync(0xffffffffu, ac, 1);
        ac += __shfl_xor_sync(0xffffffffu, ac, 2);
        ac += __shfl_xor_sync(0xffffffffu, ac, 4);
        if (c8 == 0) { s_zn[row] = az; s_cn[row] = ac; }
    }
    __syncthreads();

    // ---- Phase 2: tf32 GEMM mainloop, warp tile m16n16, k8 per step ----
    const int lane = t & 31, wid = t >> 5;
    const int wm = wid >> 2, wn = wid & 3;
    const int tile = lane >> 3, rit = lane & 7;

    const int arow = wm * 16 + 8 * (tile & 1) + rit;
    const int acb = tile >> 1;                  // chunk parity (k half of 8)
    const unsigned abase = sb + OFF_Z + arow * 1024;
    const int axor = arow & 7;

    const int brow = wn * 16 + 8 * (tile >> 1) + rit;
    const int bcb = tile & 1;
    const unsigned bbase = sb + OFF_C + brow * 1024;
    const int bxor = brow & 7;

    float d0[4] = {0.f, 0.f, 0.f, 0.f};   // n-half 0
    float d1[4] = {0.f, 0.f, 0.f, 0.f};   // n-half 1

    #pragma unroll
    for (int ks = 0; ks < 32; ks++) {
        const unsigned aoff = (unsigned)(((2 * ks + acb) ^ axor) << 4);
        const unsigned boff = (unsigned)(((2 * ks + bcb) ^ bxor) << 4);
        unsigned a[4], b[4];
        LDSM4(a, abase + aoff);
        LDSM4(b, bbase + boff);
        MMA_TF32(d0, a, b[0], b[1]);
        MMA_TF32(d1, a, b[2], b[3]);
    }

    // ---- Phase 3: epilogue -> Q ----
    const int gid = lane >> 2, tig = lane & 3;
    const int R0 = wm * 16 + gid, R1 = R0 + 8;
    const float znA = s_zn[R0], znB = s_zn[R1];
    const int c00 = wn * 16 + 2 * tig;
    const int c10 = c00 + 8;
    const float cnA0 = s_cn[c00], cnA1 = s_cn[c00 + 1];
    const float cnB0 = s_cn[c10], cnB1 = s_cn[c10 + 1];

    float q00 = frcp_ap(1.f + fsqrt_ap(fmaxf(fmaf(-2.f, d0[0], znA + cnA0), 0.f)));
    float q01 = frcp_ap(1.f + fsqrt_ap(fmaxf(fmaf(-2.f, d0[1], znA + cnA1), 0.f)));
    float q02 = frcp_ap(1.f + fsqrt_ap(fmaxf(fmaf(-2.f, d0[2], znB + cnA0), 0.f)));
    float q03 = frcp_ap(1.f + fsqrt_ap(fmaxf(fmaf(-2.f, d0[3], znB + cnA1), 0.f)));
    float q10 = frcp_ap(1.f + fsqrt_ap(fmaxf(fmaf(-2.f, d1[0], znA + cnB0), 0.f)));
    float q11 = frcp_ap(1.f + fsqrt_ap(fmaxf(fmaf(-2.f, d1[1], znA + cnB1), 0.f)));
    float q12 = frcp_ap(1.f + fsqrt_ap(fmaxf(fmaf(-2.f, d1[2], znB + cnB0), 0.f)));
    float q13 = frcp_ap(1.f + fsqrt_ap(fmaxf(fmaf(-2.f, d1[3], znB + cnB1), 0.f)));

    float rs0 = (q00 + q01) + (q10 + q11);
    float rs1 = (q02 + q03) + (q12 + q13);
    rs0 += __shfl_xor_sync(0xffffffffu, rs0, 1);
    rs0 += __shfl_xor_sync(0xffffffffu, rs0, 2);
    rs1 += __shfl_xor_sync(0xffffffffu, rs1, 1);
    rs1 += __shfl_xor_sync(0xffffffffu, rs1, 2);
    if (tig == 0) { atomicAdd(&s_rs[R0], rs0); atomicAdd(&s_rs[R1], rs1); }
    __syncthreads();

    const float ir0 = frcp_ap(s_rs[R0]), ir1 = frcp_ap(s_rs[R1]);
    q00 *= ir0; q01 *= ir0; q10 *= ir0; q11 *= ir0;
    q02 *= ir1; q03 *= ir1; q12 *= ir1; q13 *= ir1;

    const int gA = blockIdx.x * RPB + R0;
    const int gB = blockIdx.x * RPB + R1;
    *(float2*)(Q + (size_t)gA * NC + c00) = make_float2(q00, q01);
    *(float2*)(Q + (size_t)gB * NC + c00) = make_float2(q02, q03);
    *(float2*)(Q + (size_t)gA * NC + c10) = make_float2(q10, q11);
    *(float2*)(Q + (size_t)gB * NC + c10) = make_float2(q12, q13);

    float cA0 = q00 + q02, cA1 = q01 + q03;
    float cB0 = q10 + q12, cB1 = q11 + q13;
    #pragma unroll
    for (int m = 4; m <= 16; m <<= 1) {
        cA0 += __shfl_xor_sync(0xffffffffu, cA0, m);
        cA1 += __shfl_xor_sync(0xffffffffu, cA1, m);
        cB0 += __shfl_xor_sync(0xffffffffu, cB0, m);
        cB1 += __shfl_xor_sync(0xffffffffu, cB1, m);
    }
    if (lane < 4) {
        atomicAdd(&s_cs[c00], cA0);
        atomicAdd(&s_cs[c00 + 1], cA1);
        atomicAdd(&s_cs[c10], cB0);
        atomicAdd(&s_cs[c10 + 1], cB1);
    }
    __syncthreads();

    // publish block partial colsums (transposed: [col][block])
    if (t < NC) g_partT[t * NBLK + blockIdx.x] = s_cs[t];
    __threadfence();
    __syncthreads();

    // ---- single-wave grid sync (epoch ticket; replay-deterministic) ----
    if (t == 0) {
        unsigned ticket;
        asm volatile("atom.global.add.release.gpu.u32 %0, [%1], 1;"
                     : "=r"(ticket) : "l"(&g_arrive) : "memory");
        const unsigned target = (ticket / NBLK + 1u) * NBLK;
        unsigned v;
        do {
            asm volatile("ld.global.acquire.gpu.u32 %0, [%1];"
                         : "=r"(v) : "l"(&g_arrive) : "memory");
        } while (v < target);
    }
    __syncthreads();
    __threadfence();

    // total column sums: 8 segments x 16 contiguous floats per column
    {
        const int col = t >> 3, seg = t & 7;
        const float4* p4 = (const float4*)(g_partT + col * NBLK + seg * 16);
        float4 u = __ldcg(p4);
        float4 w = __ldcg(p4 + 1);
        float4 x = __ldcg(p4 + 2);
        float4 y = __ldcg(p4 + 3);
        float s = (((u.x + u.y) + (u.z + u.w)) + ((w.x + w.y) + (w.z + w.w)))
                + (((x.x + x.y) + (x.z + x.w)) + ((y.x + y.y) + (y.z + y.w)));
        s += __shfl_xor_sync(0xffffffffu, s, 1);
        s += __shfl_xor_sync(0xffffffffu, s, 2);
        s += __shfl_xor_sync(0xffffffffu, s, 4);
        if (seg == 0) s_ct[col] = s;
    }
    __syncthreads();

    // ---- Phase 4: P from in-register Q ----
    const float icA0 = frcp_ap(s_ct[c00]), icA1 = frcp_ap(s_ct[c00 + 1]);
    const float icB0 = frcp_ap(s_ct[c10]), icB1 = frcp_ap(s_ct[c10 + 1]);

    float p00 = q00 * q00 * icA0, p01 = q01 * q01 * icA1;
    float p02 = q02 * q02 * icA0, p03 = q03 * q03 * icA1;
    float p10 = q10 * q10 * icB0, p11 = q11 * q11 * icB1;
    float p12 = q12 * q12 * icB0, p13 = q13 * q13 * icB1;

    float ps0 = (p00 + p01) + (p10 + p11);
    float ps1 = (p02 + p03) + (p12 + p13);
    ps0 += __shfl_xor_sync(0xffffffffu, ps0, 1);
    ps0 += __shfl_xor_sync(0xffffffffu, ps0, 2);
    ps1 += __shfl_xor_sync(0xffffffffu, ps1, 1);
    ps1 += __shfl_xor_sync(0xffffffffu, ps1, 2);
    if (tig == 0) { atomicAdd(&s_pr[R0], ps0); atomicAdd(&s_pr[R1], ps1); }
    __syncthreads();

    const float ip0 = frcp_ap(s_pr[R0]), ip1 = frcp_ap(s_pr[R1]);
    *(float2*)(P + (size_t)gA * NC + c00) = make_float2(p00 * ip0, p01 * ip0);
    *(float2*)(P + (size_t)gB * NC + c00) = make_float2(p02 * ip1, p03 * ip1);
    *(float2*)(P + (size_t)gA * NC + c10) = make_float2(p10 * ip0, p11 * ip0);
    *(float2*)(P + (size_t)gB * NC + c10) = make_float2(p12 * ip1, p13 * ip1);
}

extern "C" void kernel_launch(void* const* d_in, const int* in_sizes, int n_in,
                              void* d_out, int out_size) {
    const float* z    = (const float*)d_in[0];   // (8192, 256) f32
    const float* cent = (const float*)d_in[1];   // (64, 256)   f32
    float* Q = (float*)d_out;
    float* P = Q + (size_t)NR * NC;

    cudaFuncSetAttribute(fused_kernel, cudaFuncAttributeMaxDynamicSharedMemorySize, SMEM_B);
    fused_kernel<<<NBLK, TPB, SMEM_B>>>(z, cent, Q, P);
}